// round 5
// baseline (speedup 1.0000x reference)
#include <cuda_runtime.h>

#define N_NODES 50000
#define N_EDGES 800000
#define F_IN    512
#define F_HID   64
#define F_OUT   16

// ---------------- scratch (device globals; no allocations) ----------------
__device__ __align__(16) float g_dinv[N_NODES];
__device__ __align__(16) float g_H1[(size_t)N_NODES * F_HID];
__device__ __align__(16) float g_A1[(size_t)N_NODES * F_HID];
__device__ __align__(16) float g_H2[(size_t)N_NODES * F_OUT];
__device__ __align__(16) float g_O [(size_t)N_NODES * F_OUT];

// ---------------- degree / norm ----------------
__global__ void k_deg_init(int n) {
    int i = blockIdx.x * blockDim.x + threadIdx.x;
    if (i < n) g_dinv[i] = 1.0f;   // self loop
}

__global__ void k_deg_count(const int* __restrict__ dst, int E, int n) {
    int e = blockIdx.x * blockDim.x + threadIdx.x;
    if (e >= E) return;
    int d = dst[e];
    if ((unsigned)d < (unsigned)n) atomicAdd(&g_dinv[d], 1.0f);
}

__global__ void k_rsqrt(int n) {
    int i = blockIdx.x * blockDim.x + threadIdx.x;
    if (i < n) g_dinv[i] = rsqrtf(g_dinv[i]);
}

// ---------------- GEMM1: g_H1[N,64] = X[N,512] @ W[512,64] ----------------
__global__ void __launch_bounds__(256) k_gemm1(const float* __restrict__ X,
                                               const float* __restrict__ W,
                                               int N) {
    __shared__ float As[16][128];   // [k][m]
    __shared__ float Bs[16][64];    // [k][n]

    const int tid = threadIdx.x;
    const int block_row = blockIdx.x * 128;
    const int tm = tid >> 4;
    const int tn = tid & 15;
    const int m0 = tm * 8;
    const int n0 = tn * 4;

    float acc[8][4];
#pragma unroll
    for (int i = 0; i < 8; i++)
#pragma unroll
        for (int j = 0; j < 4; j++) acc[i][j] = 0.0f;

    for (int k0 = 0; k0 < F_IN; k0 += 16) {
#pragma unroll
        for (int it = 0; it < 2; it++) {
            int idx  = tid + it * 256;
            int arow = idx >> 2;
            int acol = (idx & 3) * 4;
            int gr   = block_row + arow;
            float4 v = make_float4(0.f, 0.f, 0.f, 0.f);
            if (gr < N) v = *(const float4*)(X + (size_t)gr * F_IN + k0 + acol);
            As[acol + 0][arow] = v.x;
            As[acol + 1][arow] = v.y;
            As[acol + 2][arow] = v.z;
            As[acol + 3][arow] = v.w;
        }
        {
            int brow = tid >> 4;
            int bcol = (tid & 15) * 4;
            *(float4*)(&Bs[brow][bcol]) =
                *(const float4*)(W + (size_t)(k0 + brow) * F_HID + bcol);
        }
        __syncthreads();

#pragma unroll
        for (int k = 0; k < 16; k++) {
            float a[8], b[4];
#pragma unroll
            for (int i = 0; i < 8; i++) a[i] = As[k][m0 + i];
#pragma unroll
            for (int j = 0; j < 4; j++) b[j] = Bs[k][n0 + j];
#pragma unroll
            for (int i = 0; i < 8; i++)
#pragma unroll
                for (int j = 0; j < 4; j++) acc[i][j] += a[i] * b[j];
        }
        __syncthreads();
    }

#pragma unroll
    for (int i = 0; i < 8; i++) {
        int gr = block_row + m0 + i;
        if (gr < N) {
            float4 v = make_float4(acc[i][0], acc[i][1], acc[i][2], acc[i][3]);
            *(float4*)(g_H1 + (size_t)gr * F_HID + n0) = v;
        }
    }
}

// ---------- layer-1 init: A1[i*64+c] = H1[i*64+c]*dinv[i]^2 + b1[c] ----------
__global__ void k_selfloop_bias1(const float* __restrict__ b, int n) {
    int t = blockIdx.x * blockDim.x + threadIdx.x;
    if (t >= n * F_HID) return;
    int i = t >> 6;
    int c = t & 63;
    float s = g_dinv[i];
    g_A1[t] = g_H1[t] * (s * s) + b[c];
}

// ---------- layer-1 scatter: one scalar atomic per (edge, feature) ----------
__global__ void k_scatter1(const int* __restrict__ src,
                           const int* __restrict__ dst, int E, int n) {
    long long t = (long long)blockIdx.x * blockDim.x + threadIdx.x;
    if (t >= (long long)E * F_HID) return;
    int e = (int)(t >> 6);
    int c = (int)(t & 63);
    int s = src[e];
    int d = dst[e];
    if ((unsigned)s >= (unsigned)n || (unsigned)d >= (unsigned)n) return;
    float nrm = g_dinv[s] * g_dinv[d];
    atomicAdd(&g_A1[(size_t)d * F_HID + c], g_H1[(size_t)s * F_HID + c] * nrm);
}

// ---------------- relu ----------------
__global__ void k_relu(int n) {
    int i = blockIdx.x * blockDim.x + threadIdx.x;
    if (i < n) g_A1[i] = fmaxf(g_A1[i], 0.f);
}

// ---------------- GEMM2: g_H2[N,16] = g_A1[N,64] @ W[64,16] ----------------
__global__ void __launch_bounds__(256) k_gemm2(const float* __restrict__ W, int N) {
    __shared__ float Ws[F_HID * F_OUT];
    for (int i = threadIdx.x; i < F_HID * F_OUT; i += 256) Ws[i] = W[i];
    __syncthreads();

    int row = blockIdx.x * 256 + threadIdx.x;
    if (row >= N) return;

    float acc[F_OUT];
#pragma unroll
    for (int j = 0; j < F_OUT; j++) acc[j] = 0.f;

    const float* ar = g_A1 + (size_t)row * F_HID;
#pragma unroll 8
    for (int k = 0; k < F_HID; k++) {
        float xv = ar[k];
#pragma unroll
        for (int j = 0; j < F_OUT; j++) acc[j] += xv * Ws[k * F_OUT + j];
    }
#pragma unroll
    for (int j = 0; j < F_OUT; j++)
        g_H2[(size_t)row * F_OUT + j] = acc[j];
}

// ---------- layer-2 init: O[i*16+c] = H2[i*16+c]*dinv[i]^2 + b2[c] ----------
__global__ void k_selfloop_bias2(const float* __restrict__ b, int n) {
    int t = blockIdx.x * blockDim.x + threadIdx.x;
    if (t >= n * F_OUT) return;
    int i = t >> 4;
    int c = t & 15;
    float s = g_dinv[i];
    g_O[t] = g_H2[t] * (s * s) + b[c];
}

// ---------- layer-2 scatter: one scalar atomic per (edge, feature) ----------
__global__ void k_scatter2(const int* __restrict__ src,
                           const int* __restrict__ dst, int E, int n) {
    long long t = (long long)blockIdx.x * blockDim.x + threadIdx.x;
    if (t >= (long long)E * F_OUT) return;
    int e = (int)(t >> 4);
    int c = (int)(t & 15);
    int s = src[e];
    int d = dst[e];
    if ((unsigned)s >= (unsigned)n || (unsigned)d >= (unsigned)n) return;
    float nrm = g_dinv[s] * g_dinv[d];
    atomicAdd(&g_O[(size_t)d * F_OUT + c], g_H2[(size_t)s * F_OUT + c] * nrm);
}

// ---------------- final copy: out = g_O ----------------
__global__ void k_copy_out(float* __restrict__ out, int n) {
    int i = blockIdx.x * blockDim.x + threadIdx.x;
    if (i < n) out[i] = g_O[i];
}

// ---------------- launcher ----------------
extern "C" void kernel_launch(void* const* d_in, const int* in_sizes, int n_in,
                              void* d_out, int out_size) {
    const float* x  = (const float*)d_in[0];
    const int*   ei = (const int*)d_in[1];     // int32 edge_index (harness dtype)
    const float* W1 = (const float*)d_in[2];
    const float* b1 = (const float*)d_in[3];
    const float* W2 = (const float*)d_in[4];
    const float* b2 = (const float*)d_in[5];
    float*       out = (float*)d_out;

    const int N = in_sizes[0] / F_IN;
    const int E = in_sizes[1] / 2;
    const int* src = ei;
    const int* dst = ei + E;

    const int T = 256;

    // degree -> dinv
    k_deg_init<<<(N + T - 1) / T, T>>>(N);
    k_deg_count<<<(E + T - 1) / T, T>>>(dst, E, N);
    k_rsqrt<<<(N + T - 1) / T, T>>>(N);

    // layer 1
    k_gemm1<<<(N + 127) / 128, T>>>(x, W1, N);
    {
        long long work = (long long)N * F_HID;
        k_selfloop_bias1<<<(unsigned)((work + T - 1) / T), T>>>(b1, N);
    }
    {
        long long work = (long long)E * F_HID;
        k_scatter1<<<(unsigned)((work + T - 1) / T), T>>>(src, dst, E, N);
    }
    {
        int n = N * F_HID;
        k_relu<<<(n + T - 1) / T, T>>>(n);
    }

    // layer 2
    k_gemm2<<<(N + T - 1) / T, T>>>(W2, N);
    {
        long long work = (long long)N * F_OUT;
        k_selfloop_bias2<<<(unsigned)((work + T - 1) / T), T>>>(b2, N);
    }
    {
        long long work = (long long)E * F_OUT;
        k_scatter2<<<(unsigned)((work + T - 1) / T), T>>>(src, dst, E, N);
    }
    {
        int n = N * F_OUT;
        k_copy_out<<<(n + T - 1) / T, T>>>(out, n);
    }
}

// round 7
// speedup vs baseline: 1.4617x; 1.4617x over previous
#include <cuda_runtime.h>

#define N_NODES 50000
#define N_EDGES 800000
#define F_IN    512
#define F_HID   64
#define F_OUT   16

// ---------------- scratch (device globals; no allocations) ----------------
__device__ __align__(16) float g_dinv[N_NODES];
__device__ __align__(16) float g_H1[(size_t)N_NODES * F_HID];
__device__ __align__(16) float g_A1[(size_t)N_NODES * F_HID];
__device__ __align__(16) float g_H2[(size_t)N_NODES * F_OUT];

// ---------------- degree / norm ----------------
__global__ void k_deg_init(int n) {
    int i = blockIdx.x * blockDim.x + threadIdx.x;
    if (i < n) g_dinv[i] = 1.0f;   // self loop
}

__global__ void k_deg_count(const int* __restrict__ dst, int E, int n) {
    int e = blockIdx.x * blockDim.x + threadIdx.x;
    if (e >= E) return;
    int d = dst[e];
    if ((unsigned)d < (unsigned)n) atomicAdd(&g_dinv[d], 1.0f);
}

__global__ void k_rsqrt(int n) {
    int i = blockIdx.x * blockDim.x + threadIdx.x;
    if (i < n) g_dinv[i] = rsqrtf(g_dinv[i]);
}

// ---------------- GEMM1: H1 = X @ W1 ; A1 = H1*dinv^2 + b1 (fused epilogue) ----
// 256x64 block tile, BK=16, 256 threads, 8x8 per thread, double-buffered smem.
#define BM 256
#define BK 16
#define APAD 4   // pad to keep float4-aligned rows (stride 260 floats = 1040B)
__global__ void __launch_bounds__(256) k_gemm1(const float* __restrict__ X,
                                               const float* __restrict__ W,
                                               const float* __restrict__ b1,
                                               int N) {
    __shared__ float As[2][BK][BM + APAD];
    __shared__ float Bs[2][BK][F_HID];

    const int tid = threadIdx.x;
    const int block_row = blockIdx.x * BM;
    const int tm = tid >> 3;        // 0..31
    const int tn = tid & 7;         // 0..7
    const int m0 = tm * 8;
    const int n0 = tn * 8;

    float acc[8][8];
#pragma unroll
    for (int i = 0; i < 8; i++)
#pragma unroll
        for (int j = 0; j < 8; j++) acc[i][j] = 0.0f;

    const int brow = tid >> 4;           // 0..15
    const int bcol = (tid & 15) * 4;     // 0..60

    // initial tile -> buffer 0
#pragma unroll
    for (int it = 0; it < 4; it++) {
        int idx  = it * 256 + tid;
        int arow = idx >> 2;
        int acol = (idx & 3) * 4;
        int gr   = block_row + arow;
        float4 v = (gr < N) ? *(const float4*)(X + (size_t)gr * F_IN + acol)
                            : make_float4(0.f, 0.f, 0.f, 0.f);
        As[0][acol + 0][arow] = v.x;
        As[0][acol + 1][arow] = v.y;
        As[0][acol + 2][arow] = v.z;
        As[0][acol + 3][arow] = v.w;
    }
    *(float4*)&Bs[0][brow][bcol] = *(const float4*)(W + (size_t)brow * F_HID + bcol);
    __syncthreads();

    const int NT = F_IN / BK;   // 32
    float4 pa[4];
    float4 pb;

    for (int t0 = 0; t0 < NT; t0++) {
        int cur = t0 & 1;
        int nxt = cur ^ 1;
        if (t0 + 1 < NT) {
            int k0n = (t0 + 1) * BK;
#pragma unroll
            for (int it = 0; it < 4; it++) {
                int idx  = it * 256 + tid;
                int arow = idx >> 2;
                int acol = (idx & 3) * 4;
                int gr   = block_row + arow;
                pa[it] = (gr < N) ? *(const float4*)(X + (size_t)gr * F_IN + k0n + acol)
                                  : make_float4(0.f, 0.f, 0.f, 0.f);
            }
            pb = *(const float4*)(W + (size_t)(k0n + brow) * F_HID + bcol);
        }
#pragma unroll
        for (int k = 0; k < BK; k++) {
            float a[8], b[8];
            *(float4*)&a[0] = *(const float4*)&As[cur][k][m0];
            *(float4*)&a[4] = *(const float4*)&As[cur][k][m0 + 4];
            *(float4*)&b[0] = *(const float4*)&Bs[cur][k][n0];
            *(float4*)&b[4] = *(const float4*)&Bs[cur][k][n0 + 4];
#pragma unroll
            for (int i = 0; i < 8; i++)
#pragma unroll
                for (int j = 0; j < 8; j++) acc[i][j] += a[i] * b[j];
        }
        if (t0 + 1 < NT) {
#pragma unroll
            for (int it = 0; it < 4; it++) {
                int idx  = it * 256 + tid;
                int arow = idx >> 2;
                int acol = (idx & 3) * 4;
                As[nxt][acol + 0][arow] = pa[it].x;
                As[nxt][acol + 1][arow] = pa[it].y;
                As[nxt][acol + 2][arow] = pa[it].z;
                As[nxt][acol + 3][arow] = pa[it].w;
            }
            *(float4*)&Bs[nxt][brow][bcol] = pb;
            __syncthreads();
        }
    }

    // epilogue: H1 = acc ; A1 = acc*dinv^2 + b1
    float4 bb0 = *(const float4*)(b1 + n0);
    float4 bb1 = *(const float4*)(b1 + n0 + 4);
#pragma unroll
    for (int i = 0; i < 8; i++) {
        int gr = block_row + m0 + i;
        if (gr >= N) break;
        float s = g_dinv[gr];
        s = s * s;
        float4 h0 = make_float4(acc[i][0], acc[i][1], acc[i][2], acc[i][3]);
        float4 h1 = make_float4(acc[i][4], acc[i][5], acc[i][6], acc[i][7]);
        *(float4*)(g_H1 + (size_t)gr * F_HID + n0)     = h0;
        *(float4*)(g_H1 + (size_t)gr * F_HID + n0 + 4) = h1;
        float4 a0 = make_float4(h0.x * s + bb0.x, h0.y * s + bb0.y,
                                h0.z * s + bb0.z, h0.w * s + bb0.w);
        float4 a1 = make_float4(h1.x * s + bb1.x, h1.y * s + bb1.y,
                                h1.z * s + bb1.z, h1.w * s + bb1.w);
        *(float4*)(g_A1 + (size_t)gr * F_HID + n0)     = a0;
        *(float4*)(g_A1 + (size_t)gr * F_HID + n0 + 4) = a1;
    }
}

// ---------- layer-1 scatter: one float4 atomic per (edge, 4-feature chunk) ----
__global__ void k_scatter1(const int* __restrict__ src,
                           const int* __restrict__ dst, int E, int n) {
    long long t = (long long)blockIdx.x * blockDim.x + threadIdx.x;
    if (t >= (long long)E * (F_HID / 4)) return;
    int e  = (int)(t >> 4);
    int c4 = (int)(t & 15);
    int s = src[e];
    int d = dst[e];
    if ((unsigned)s >= (unsigned)n || (unsigned)d >= (unsigned)n) return;
    float nrm = g_dinv[s] * g_dinv[d];
    float4 v = ((const float4*)g_H1)[(size_t)s * (F_HID / 4) + c4];
    v.x *= nrm; v.y *= nrm; v.z *= nrm; v.w *= nrm;
    atomicAdd(((float4*)g_A1) + (size_t)d * (F_HID / 4) + c4, v);
}

// ---------------- GEMM2: H2 = relu(A1) @ W2 ; out-init = H2*dinv^2 + b2 ------
// 128 rows per block, 256 threads; A1 tile staged in smem (relu on load).
__global__ void __launch_bounds__(256) k_gemm2(const float* __restrict__ W2,
                                               const float* __restrict__ b2,
                                               float* __restrict__ out, int N) {
    __shared__ float At[128][F_HID + 4];   // stride 68 floats = 272B (16B multiple)
    __shared__ float Ws[F_HID * F_OUT];

    const int tid = threadIdx.x;
    for (int i = tid; i < F_HID * F_OUT; i += 256) Ws[i] = W2[i];

    const int row0 = blockIdx.x * 128;
#pragma unroll
    for (int it = 0; it < 8; it++) {
        int idx = it * 256 + tid;     // 0..2047
        int r   = idx >> 4;
        int c4  = idx & 15;
        int gr  = row0 + r;
        float4 v = (gr < N) ? ((const float4*)g_A1)[(size_t)gr * (F_HID / 4) + c4]
                            : make_float4(0.f, 0.f, 0.f, 0.f);
        v.x = fmaxf(v.x, 0.f); v.y = fmaxf(v.y, 0.f);
        v.z = fmaxf(v.z, 0.f); v.w = fmaxf(v.w, 0.f);
        *(float4*)&At[r][c4 * 4] = v;
    }
    __syncthreads();

    const int r  = tid >> 1;            // 0..127
    const int j0 = (tid & 1) * 8;       // 0 or 8
    const int gr = row0 + r;
    if (gr >= N) return;

    float acc[8];
#pragma unroll
    for (int j = 0; j < 8; j++) acc[j] = 0.f;
#pragma unroll
    for (int k = 0; k < F_HID; k++) {
        float xv = At[r][k];
#pragma unroll
        for (int j = 0; j < 8; j++) acc[j] += xv * Ws[k * F_OUT + j0 + j];
    }

    float s = g_dinv[gr];
    s = s * s;
    float4 bb0 = *(const float4*)(b2 + j0);
    float4 bb1 = *(const float4*)(b2 + j0 + 4);
    float4 h0 = make_float4(acc[0], acc[1], acc[2], acc[3]);
    float4 h1 = make_float4(acc[4], acc[5], acc[6], acc[7]);
    *(float4*)(g_H2 + (size_t)gr * F_OUT + j0)     = h0;
    *(float4*)(g_H2 + (size_t)gr * F_OUT + j0 + 4) = h1;
    float4 o0 = make_float4(h0.x * s + bb0.x, h0.y * s + bb0.y,
                            h0.z * s + bb0.z, h0.w * s + bb0.w);
    float4 o1 = make_float4(h1.x * s + bb1.x, h1.y * s + bb1.y,
                            h1.z * s + bb1.z, h1.w * s + bb1.w);
    *(float4*)(out + (size_t)gr * F_OUT + j0)     = o0;
    *(float4*)(out + (size_t)gr * F_OUT + j0 + 4) = o1;
}

// ---------- layer-2 scatter: one float4 atomic per (edge, 4-feature chunk) ----
__global__ void k_scatter2(const int* __restrict__ src,
                           const int* __restrict__ dst,
                           float* __restrict__ out, int E, int n) {
    long long t = (long long)blockIdx.x * blockDim.x + threadIdx.x;
    if (t >= (long long)E * (F_OUT / 4)) return;
    int e  = (int)(t >> 2);
    int c4 = (int)(t & 3);
    int s = src[e];
    int d = dst[e];
    if ((unsigned)s >= (unsigned)n || (unsigned)d >= (unsigned)n) return;
    float nrm = g_dinv[s] * g_dinv[d];
    float4 v = ((const float4*)g_H2)[(size_t)s * (F_OUT / 4) + c4];
    v.x *= nrm; v.y *= nrm; v.z *= nrm; v.w *= nrm;
    atomicAdd(((float4*)out) + (size_t)d * (F_OUT / 4) + c4, v);
}

// ---------------- launcher ----------------
extern "C" void kernel_launch(void* const* d_in, const int* in_sizes, int n_in,
                              void* d_out, int out_size) {
    const float* x  = (const float*)d_in[0];
    const int*   ei = (const int*)d_in[1];     // int32 edge_index
    const float* W1 = (const float*)d_in[2];
    const float* b1 = (const float*)d_in[3];
    const float* W2 = (const float*)d_in[4];
    const float* b2 = (const float*)d_in[5];
    float*       out = (float*)d_out;

    const int N = in_sizes[0] / F_IN;
    const int E = in_sizes[1] / 2;
    const int* src = ei;
    const int* dst = ei + E;

    const int T = 256;

    // degree -> dinv
    k_deg_init<<<(N + T - 1) / T, T>>>(N);
    k_deg_count<<<(E + T - 1) / T, T>>>(dst, E, N);
    k_rsqrt<<<(N + T - 1) / T, T>>>(N);

    // layer 1: GEMM(+bias/selfloop epilogue), scatter
    k_gemm1<<<(N + BM - 1) / BM, T>>>(x, W1, b1, N);
    {
        long long work = (long long)E * (F_HID / 4);
        k_scatter1<<<(unsigned)((work + T - 1) / T), T>>>(src, dst, E, N);
    }

    // layer 2: GEMM(relu on load, +bias/selfloop epilogue -> out), scatter -> out
    k_gemm2<<<(N + 127) / 128, T>>>(W2, b2, out, N);
    {
        long long work = (long long)E * (F_OUT / 4);
        k_scatter2<<<(unsigned)((work + T - 1) / T), T>>>(src, dst, out, E, N);
    }
}

// round 8
// speedup vs baseline: 1.9056x; 1.3037x over previous
#include <cuda_runtime.h>

#define N_NODES 50000
#define N_EDGES 800000
#define F_IN    512
#define F_HID   64
#define F_OUT   16

// ---------------- scratch (device globals; no allocations) ----------------
__device__ __align__(16) float g_dinv[N_NODES];
__device__ __align__(16) float g_H1[(size_t)N_NODES * F_HID];  // H1 * dinv[row]
__device__ __align__(16) float g_A1[(size_t)N_NODES * F_HID];
__device__ __align__(16) float g_H2[(size_t)N_NODES * F_OUT];  // H2 * dinv[row]

// ---------------- degree / norm ----------------
__global__ void k_deg_init(int n) {
    int i = blockIdx.x * blockDim.x + threadIdx.x;
    if (i < n) g_dinv[i] = 1.0f;   // self loop
}

__global__ void k_deg_count(const int* __restrict__ dst, int E, int n) {
    int e = blockIdx.x * blockDim.x + threadIdx.x;
    if (e >= E) return;
    int d = dst[e];
    if ((unsigned)d < (unsigned)n) atomicAdd(&g_dinv[d], 1.0f);
}

__global__ void k_rsqrt(int n) {
    int i = blockIdx.x * blockDim.x + threadIdx.x;
    if (i < n) g_dinv[i] = rsqrtf(g_dinv[i]);
}

// ---------------- GEMM1: H1' = (X@W1)*dinv ; A1 = H1'*dinv + b1 ----------------
// 128x64 tile, BK=16, 128 threads, 8x8 per thread, single smem buffer +
// register prefetch. Whole grid (391 CTAs) resident in one wave at 4 CTA/SM.
#define BM 128
#define BK 16
__global__ void __launch_bounds__(128) k_gemm1(const float* __restrict__ X,
                                               const float* __restrict__ W,
                                               const float* __restrict__ b1,
                                               int N) {
    __shared__ float As[BK][BM + 4];   // stride 132 floats (16B multiple)
    __shared__ float Bs[BK][F_HID];

    const int tid = threadIdx.x;
    const int block_row = blockIdx.x * BM;
    const int tm = tid >> 3;        // 0..15
    const int tn = tid & 7;         // 0..7
    const int m0 = tm * 8;
    const int n0 = tn * 8;

    float acc[8][8];
#pragma unroll
    for (int i = 0; i < 8; i++)
#pragma unroll
        for (int j = 0; j < 8; j++) acc[i][j] = 0.0f;

    // loader indexing
    // A: 512 float4 per tile, 4/thread: arow = idx>>2 (0..127), acol = (idx&3)*4
    // B: 256 float4 per tile, 2/thread: brow = idx>>4 (0..15),  bcol = (idx&15)*4

    // tile 0 -> smem
#pragma unroll
    for (int it = 0; it < 4; it++) {
        int idx  = it * 128 + tid;
        int arow = idx >> 2;
        int acol = (idx & 3) * 4;
        int gr   = block_row + arow;
        float4 v = (gr < N) ? *(const float4*)(X + (size_t)gr * F_IN + acol)
                            : make_float4(0.f, 0.f, 0.f, 0.f);
        As[acol + 0][arow] = v.x;
        As[acol + 1][arow] = v.y;
        As[acol + 2][arow] = v.z;
        As[acol + 3][arow] = v.w;
    }
#pragma unroll
    for (int it = 0; it < 2; it++) {
        int idx  = it * 128 + tid;
        int brow = idx >> 4;
        int bcol = (idx & 15) * 4;
        *(float4*)&Bs[brow][bcol] = *(const float4*)(W + (size_t)brow * F_HID + bcol);
    }
    __syncthreads();

    const int NT = F_IN / BK;   // 32
    float4 pa[4];
    float4 pb[2];

    for (int t0 = 0; t0 < NT; t0++) {
        // prefetch next tile into registers (hides global latency under compute)
        if (t0 + 1 < NT) {
            int k0n = (t0 + 1) * BK;
#pragma unroll
            for (int it = 0; it < 4; it++) {
                int idx  = it * 128 + tid;
                int arow = idx >> 2;
                int acol = (idx & 3) * 4;
                int gr   = block_row + arow;
                pa[it] = (gr < N) ? *(const float4*)(X + (size_t)gr * F_IN + k0n + acol)
                                  : make_float4(0.f, 0.f, 0.f, 0.f);
            }
#pragma unroll
            for (int it = 0; it < 2; it++) {
                int idx  = it * 128 + tid;
                int brow = idx >> 4;
                int bcol = (idx & 15) * 4;
                pb[it] = *(const float4*)(W + (size_t)(k0n + brow) * F_HID + bcol);
            }
        }
        // compute on current buffer
#pragma unroll
        for (int k = 0; k < BK; k++) {
            float a[8], b[8];
            *(float4*)&a[0] = *(const float4*)&As[k][m0];
            *(float4*)&a[4] = *(const float4*)&As[k][m0 + 4];
            *(float4*)&b[0] = *(const float4*)&Bs[k][n0];
            *(float4*)&b[4] = *(const float4*)&Bs[k][n0 + 4];
#pragma unroll
            for (int i = 0; i < 8; i++)
#pragma unroll
                for (int j = 0; j < 8; j++) acc[i][j] += a[i] * b[j];
        }
        if (t0 + 1 < NT) {
            __syncthreads();   // all readers done
#pragma unroll
            for (int it = 0; it < 4; it++) {
                int idx  = it * 128 + tid;
                int arow = idx >> 2;
                int acol = (idx & 3) * 4;
                As[acol + 0][arow] = pa[it].x;
                As[acol + 1][arow] = pa[it].y;
                As[acol + 2][arow] = pa[it].z;
                As[acol + 3][arow] = pa[it].w;
            }
#pragma unroll
            for (int it = 0; it < 2; it++) {
                int idx  = it * 128 + tid;
                int brow = idx >> 4;
                int bcol = (idx & 15) * 4;
                *(float4*)&Bs[brow][bcol] = pb[it];
            }
            __syncthreads();   // tile visible
        }
    }

    // epilogue: H1' = acc*dinv ; A1 = H1'*dinv + b1
    float4 bb0 = *(const float4*)(b1 + n0);
    float4 bb1 = *(const float4*)(b1 + n0 + 4);
#pragma unroll
    for (int i = 0; i < 8; i++) {
        int gr = block_row + m0 + i;
        if (gr >= N) break;
        float s = g_dinv[gr];
        float4 h0 = make_float4(acc[i][0] * s, acc[i][1] * s, acc[i][2] * s, acc[i][3] * s);
        float4 h1 = make_float4(acc[i][4] * s, acc[i][5] * s, acc[i][6] * s, acc[i][7] * s);
        *(float4*)(g_H1 + (size_t)gr * F_HID + n0)     = h0;
        *(float4*)(g_H1 + (size_t)gr * F_HID + n0 + 4) = h1;
        float4 a0 = make_float4(h0.x * s + bb0.x, h0.y * s + bb0.y,
                                h0.z * s + bb0.z, h0.w * s + bb0.w);
        float4 a1 = make_float4(h1.x * s + bb1.x, h1.y * s + bb1.y,
                                h1.z * s + bb1.z, h1.w * s + bb1.w);
        *(float4*)(g_A1 + (size_t)gr * F_HID + n0)     = a0;
        *(float4*)(g_A1 + (size_t)gr * F_HID + n0 + 4) = a1;
    }
}

// ---------- layer-1 scatter: A1[dst] += H1'[src] * dinv[dst] (float4 atomic) ----
__global__ void k_scatter1(const int* __restrict__ src,
                           const int* __restrict__ dst, int E, int n) {
    long long t = (long long)blockIdx.x * blockDim.x + threadIdx.x;
    if (t >= (long long)E * (F_HID / 4)) return;
    int e  = (int)(t >> 4);
    int c4 = (int)(t & 15);
    int s = src[e];
    int d = dst[e];
    if ((unsigned)s >= (unsigned)n || (unsigned)d >= (unsigned)n) return;
    float nrm = g_dinv[d];
    float4 v = ((const float4*)g_H1)[(size_t)s * (F_HID / 4) + c4];
    v.x *= nrm; v.y *= nrm; v.z *= nrm; v.w *= nrm;
    atomicAdd(((float4*)g_A1) + (size_t)d * (F_HID / 4) + c4, v);
}

// ---------------- GEMM2: H2' = (relu(A1)@W2)*dinv ; out = H2'*dinv + b2 ------
__global__ void __launch_bounds__(256) k_gemm2(const float* __restrict__ W2,
                                               const float* __restrict__ b2,
                                               float* __restrict__ out, int N) {
    __shared__ float At[128][F_HID + 4];   // stride 68 floats = 272B
    __shared__ float Ws[F_HID * F_OUT];

    const int tid = threadIdx.x;
    for (int i = tid; i < F_HID * F_OUT; i += 256) Ws[i] = W2[i];

    const int row0 = blockIdx.x * 128;
#pragma unroll
    for (int it = 0; it < 8; it++) {
        int idx = it * 256 + tid;
        int r   = idx >> 4;
        int c4  = idx & 15;
        int gr  = row0 + r;
        float4 v = (gr < N) ? ((const float4*)g_A1)[(size_t)gr * (F_HID / 4) + c4]
                            : make_float4(0.f, 0.f, 0.f, 0.f);
        v.x = fmaxf(v.x, 0.f); v.y = fmaxf(v.y, 0.f);
        v.z = fmaxf(v.z, 0.f); v.w = fmaxf(v.w, 0.f);
        *(float4*)&At[r][c4 * 4] = v;
    }
    __syncthreads();

    const int r  = tid >> 1;
    const int j0 = (tid & 1) * 8;
    const int gr = row0 + r;
    if (gr >= N) return;

    float acc[8];
#pragma unroll
    for (int j = 0; j < 8; j++) acc[j] = 0.f;
#pragma unroll
    for (int k = 0; k < F_HID; k++) {
        float xv = At[r][k];
#pragma unroll
        for (int j = 0; j < 8; j++) acc[j] += xv * Ws[k * F_OUT + j0 + j];
    }

    float s = g_dinv[gr];
    float4 bb0 = *(const float4*)(b2 + j0);
    float4 bb1 = *(const float4*)(b2 + j0 + 4);
    float4 h0 = make_float4(acc[0] * s, acc[1] * s, acc[2] * s, acc[3] * s);
    float4 h1 = make_float4(acc[4] * s, acc[5] * s, acc[6] * s, acc[7] * s);
    *(float4*)(g_H2 + (size_t)gr * F_OUT + j0)     = h0;
    *(float4*)(g_H2 + (size_t)gr * F_OUT + j0 + 4) = h1;
    float4 o0 = make_float4(h0.x * s + bb0.x, h0.y * s + bb0.y,
                            h0.z * s + bb0.z, h0.w * s + bb0.w);
    float4 o1 = make_float4(h1.x * s + bb1.x, h1.y * s + bb1.y,
                            h1.z * s + bb1.z, h1.w * s + bb1.w);
    *(float4*)(out + (size_t)gr * F_OUT + j0)     = o0;
    *(float4*)(out + (size_t)gr * F_OUT + j0 + 4) = o1;
}

// ---------- layer-2 scatter: out[dst] += H2'[src] * dinv[dst] (float4 atomic) ----
__global__ void k_scatter2(const int* __restrict__ src,
                           const int* __restrict__ dst,
                           float* __restrict__ out, int E, int n) {
    long long t = (long long)blockIdx.x * blockDim.x + threadIdx.x;
    if (t >= (long long)E * (F_OUT / 4)) return;
    int e  = (int)(t >> 2);
    int c4 = (int)(t & 3);
    int s = src[e];
    int d = dst[e];
    if ((unsigned)s >= (unsigned)n || (unsigned)d >= (unsigned)n) return;
    float nrm = g_dinv[d];
    float4 v = ((const float4*)g_H2)[(size_t)s * (F_OUT / 4) + c4];
    v.x *= nrm; v.y *= nrm; v.z *= nrm; v.w *= nrm;
    atomicAdd(((float4*)out) + (size_t)d * (F_OUT / 4) + c4, v);
}

// ---------------- launcher ----------------
extern "C" void kernel_launch(void* const* d_in, const int* in_sizes, int n_in,
                              void* d_out, int out_size) {
    const float* x  = (const float*)d_in[0];
    const int*   ei = (const int*)d_in[1];     // int32 edge_index
    const float* W1 = (const float*)d_in[2];
    const float* b1 = (const float*)d_in[3];
    const float* W2 = (const float*)d_in[4];
    const float* b2 = (const float*)d_in[5];
    float*       out = (float*)d_out;

    const int N = in_sizes[0] / F_IN;
    const int E = in_sizes[1] / 2;
    const int* src = ei;
    const int* dst = ei + E;

    const int T = 256;

    // degree -> dinv
    k_deg_init<<<(N + T - 1) / T, T>>>(N);
    k_deg_count<<<(E + T - 1) / T, T>>>(dst, E, N);
    k_rsqrt<<<(N + T - 1) / T, T>>>(N);

    // layer 1
    k_gemm1<<<(N + BM - 1) / BM, 128>>>(x, W1, b1, N);
    {
        long long work = (long long)E * (F_HID / 4);
        k_scatter1<<<(unsigned)((work + T - 1) / T), T>>>(src, dst, E, N);
    }

    // layer 2
    k_gemm2<<<(N + 127) / 128, T>>>(W2, b2, out, N);
    {
        long long work = (long long)E * (F_OUT / 4);
        k_scatter2<<<(unsigned)((work + T - 1) / T), T>>>(src, dst, out, E, N);
    }
}

// round 10
// speedup vs baseline: 2.1767x; 1.1422x over previous
#include <cuda_runtime.h>
#include <cuda_bf16.h>
#include <cstdint>

#define N_NODES 50000
#define N_EDGES 800000
#define F_IN    512
#define F_HID   64
#define F_OUT   16

// ---------------- scratch (device globals; no allocations) ----------------
__device__ __align__(16) float g_dinv[N_NODES];
__device__ __align__(16) float g_H1[(size_t)N_NODES * F_HID];  // H1 * dinv[row]
__device__ __align__(16) float g_A1[(size_t)N_NODES * F_HID];
__device__ __align__(16) float g_H2[(size_t)N_NODES * F_OUT];  // H2 * dinv[row]
// W1^T in bf16 hi/lo: [64 n][512 k]
__device__ __align__(16) __nv_bfloat16 g_W1t_hi[(size_t)F_HID * F_IN];
__device__ __align__(16) __nv_bfloat16 g_W1t_lo[(size_t)F_HID * F_IN];

__device__ __forceinline__ uint32_t smem_u32(const void* p) {
    uint32_t a;
    asm("{ .reg .u64 t; cvta.to.shared.u64 t, %1; cvt.u32.u64 %0, t; }"
        : "=r"(a) : "l"(p));
    return a;
}

// ---------------- degree / norm ----------------
__global__ void k_deg_init(int n) {
    int i = blockIdx.x * blockDim.x + threadIdx.x;
    if (i < n) g_dinv[i] = 1.0f;
}

__global__ void k_deg_count(const int* __restrict__ dst, int E, int n) {
    int e = blockIdx.x * blockDim.x + threadIdx.x;
    if (e >= E) return;
    int d = dst[e];
    if ((unsigned)d < (unsigned)n) atomicAdd(&g_dinv[d], 1.0f);
}

__global__ void k_rsqrt(int n) {
    int i = blockIdx.x * blockDim.x + threadIdx.x;
    if (i < n) g_dinv[i] = rsqrtf(g_dinv[i]);
}

// ---------------- W1 -> W1^T bf16 hi/lo (once; tiny) ----------------
__global__ void k_convW1(const float* __restrict__ W1) {
    int t = blockIdx.x * blockDim.x + threadIdx.x;   // over 64*512
    if (t >= F_HID * F_IN) return;
    int n_ = t >> 9;          // /512
    int k  = t & 511;
    float w = W1[(size_t)k * F_HID + n_];
    __nv_bfloat16 h = __float2bfloat16_rn(w);
    __nv_bfloat16 l = __float2bfloat16_rn(w - __bfloat162float(h));
    g_W1t_hi[t] = h;
    g_W1t_lo[t] = l;
}

// ====== GEMM1 (mma.sync bf16x3): H1' = (X@W1)*dinv ; A1 = H1'*dinv + b1 ======
// 128 threads = 4 warps; CTA does 64 rows x 64 cols; warp w owns rows 16w..16w+15.
// K = 512 in 8 chunks of KC=64 (4 mma k-steps of 16 per chunk).
#define KC       64
#define NCHUNK   (F_IN / KC)        // 8
#define SROW     144                 // smem row stride bytes (64 bf16 + 16B pad)

__device__ __forceinline__ void ldmx4(uint32_t* r, uint32_t addr) {
    asm volatile("ldmatrix.sync.aligned.m8n8.x4.shared.b16 {%0,%1,%2,%3}, [%4];"
                 : "=r"(r[0]), "=r"(r[1]), "=r"(r[2]), "=r"(r[3]) : "r"(addr));
}
__device__ __forceinline__ void ldmx2(uint32_t* r, uint32_t addr) {
    asm volatile("ldmatrix.sync.aligned.m8n8.x2.shared.b16 {%0,%1}, [%2];"
                 : "=r"(r[0]), "=r"(r[1]) : "r"(addr));
}
__device__ __forceinline__ void mma16816(float* d, const uint32_t* a, const uint32_t* b) {
    asm volatile(
        "mma.sync.aligned.m16n8k16.row.col.f32.bf16.bf16.f32 "
        "{%0,%1,%2,%3}, {%4,%5,%6,%7}, {%8,%9}, {%0,%1,%2,%3};"
        : "+f"(d[0]), "+f"(d[1]), "+f"(d[2]), "+f"(d[3])
        : "r"(a[0]), "r"(a[1]), "r"(a[2]), "r"(a[3]), "r"(b[0]), "r"(b[1]));
}

__global__ void __launch_bounds__(128) k_gemm1_mma(const float* __restrict__ X,
                                                   const float* __restrict__ b1,
                                                   int N) {
    __shared__ __align__(16) uint8_t sm[4 * 64 * SROW];   // Ahi, Alo, Bhi, Blo
    uint8_t* p_ahi = sm;
    uint8_t* p_alo = sm + 64 * SROW;
    uint8_t* p_bhi = sm + 2 * 64 * SROW;
    uint8_t* p_blo = sm + 3 * 64 * SROW;
    const uint32_t s_ahi = smem_u32(p_ahi);
    const uint32_t s_alo = smem_u32(p_alo);
    const uint32_t s_bhi = smem_u32(p_bhi);
    const uint32_t s_blo = smem_u32(p_blo);

    const int tid  = threadIdx.x;
    const int wid  = tid >> 5;
    const int lane = tid & 31;
    const int block_row = blockIdx.x * 64;

    float acc[8][4];
#pragma unroll
    for (int g = 0; g < 8; g++)
#pragma unroll
        for (int j = 0; j < 4; j++) acc[g][j] = 0.f;

    // ldmatrix source addresses (per-lane, fixed row/col pattern within tile)
    // A (16x16 per warp): row = 16*wid + lane%16, col8 = (lane/16)*8
    const uint32_t a_row = 16 * wid + (lane & 15);
    const uint32_t a_c8  = (lane >> 4) * 8;
    // B (8x16 per group): row = lane%8 (+8g), col8 = ((lane>>3)&1)*8
    const uint32_t b_row = lane & 7;
    const uint32_t b_c8  = ((lane >> 3) & 1) * 8;

    for (int chunk = 0; chunk < NCHUNK; chunk++) {
        const int k0 = chunk * KC;

        // ---- stage A: 64 rows x 64 k fp32 -> bf16 hi/lo (8 float4/thread) ----
#pragma unroll
        for (int it = 0; it < 8; it++) {
            int idx = it * 128 + tid;        // 0..1023
            int row = idx >> 4;              // 0..63
            int c4  = idx & 15;              // float4 index within 64 floats
            int gr  = block_row + row;
            float4 v = (gr < N) ? *(const float4*)(X + (size_t)gr * F_IN + k0 + c4 * 4)
                                : make_float4(0.f, 0.f, 0.f, 0.f);
            __nv_bfloat162 h0 = __floats2bfloat162_rn(v.x, v.y);
            __nv_bfloat162 h1 = __floats2bfloat162_rn(v.z, v.w);
            __nv_bfloat162 l0 = __floats2bfloat162_rn(v.x - __low2float(h0),
                                                      v.y - __high2float(h0));
            __nv_bfloat162 l1 = __floats2bfloat162_rn(v.z - __low2float(h1),
                                                      v.w - __high2float(h1));
            uint32_t off = row * SROW + c4 * 8;
            *(uint32_t*)(p_ahi + off)     = *(uint32_t*)&h0;
            *(uint32_t*)(p_ahi + off + 4) = *(uint32_t*)&h1;
            *(uint32_t*)(p_alo + off)     = *(uint32_t*)&l0;
            *(uint32_t*)(p_alo + off + 4) = *(uint32_t*)&l1;
        }
        // ---- stage B: W1t hi/lo [64 n][64 k] bf16 (4 uint4/thread/buffer) ----
#pragma unroll
        for (int it = 0; it < 4; it++) {
            int idx = it * 128 + tid;        // 0..511
            int row = idx >> 3;              // 0..63
            int c   = idx & 7;               // uint4 (8 bf16) index
            size_t gsrc = (size_t)row * F_IN + k0 + c * 8;
            uint32_t off = row * SROW + c * 16;
            *(uint4*)(p_bhi + off) = *(const uint4*)(g_W1t_hi + gsrc);
            *(uint4*)(p_blo + off) = *(const uint4*)(g_W1t_lo + gsrc);
        }
        __syncthreads();

        // ---- compute: 4 k-steps x 8 col-groups x 3 mma ----
#pragma unroll
        for (int s = 0; s < 4; s++) {
            uint32_t ah[4], al[4];
            uint32_t aoff = a_row * SROW + (s * 16 + a_c8) * 2;
            ldmx4(ah, s_ahi + aoff);
            ldmx4(al, s_alo + aoff);
#pragma unroll
            for (int g = 0; g < 8; g++) {
                uint32_t bh[2], bl[2];
                uint32_t boff = (g * 8 + b_row) * SROW + (s * 16 + b_c8) * 2;
                ldmx2(bh, s_bhi + boff);
                ldmx2(bl, s_blo + boff);
                mma16816(acc[g], ah, bh);
                mma16816(acc[g], ah, bl);
                mma16816(acc[g], al, bh);
            }
        }
        __syncthreads();
    }

    // ---- epilogue: c-fragment rows r0=lane/4, r1=r0+8 ; cols 2*(lane%4)(+1) ----
    int r0 = block_row + 16 * wid + (lane >> 2);
    int r1 = r0 + 8;
    int cb = (lane & 3) * 2;
    float s0 = (r0 < N) ? g_dinv[r0] : 0.f;
    float s1 = (r1 < N) ? g_dinv[r1] : 0.f;
#pragma unroll
    for (int g = 0; g < 8; g++) {
        int col = g * 8 + cb;
        float bx = b1[col], by = b1[col + 1];
        if (r0 < N) {
            float2 h = make_float2(acc[g][0] * s0, acc[g][1] * s0);
            *(float2*)(g_H1 + (size_t)r0 * F_HID + col) = h;
            *(float2*)(g_A1 + (size_t)r0 * F_HID + col) =
                make_float2(h.x * s0 + bx, h.y * s0 + by);
        }
        if (r1 < N) {
            float2 h = make_float2(acc[g][2] * s1, acc[g][3] * s1);
            *(float2*)(g_H1 + (size_t)r1 * F_HID + col) = h;
            *(float2*)(g_A1 + (size_t)r1 * F_HID + col) =
                make_float2(h.x * s1 + bx, h.y * s1 + by);
        }
    }
}

// ---------- layer-1 scatter: A1[dst] += H1'[src] * dinv[dst] (float4 atomic) ----
__global__ void k_scatter1(const int* __restrict__ src,
                           const int* __restrict__ dst, int E, int n) {
    long long t = (long long)blockIdx.x * blockDim.x + threadIdx.x;
    if (t >= (long long)E * (F_HID / 4)) return;
    int e  = (int)(t >> 4);
    int c4 = (int)(t & 15);
    int s = src[e];
    int d = dst[e];
    if ((unsigned)s >= (unsigned)n || (unsigned)d >= (unsigned)n) return;
    float nrm = g_dinv[d];
    float4 v = ((const float4*)g_H1)[(size_t)s * (F_HID / 4) + c4];
    v.x *= nrm; v.y *= nrm; v.z *= nrm; v.w *= nrm;
    atomicAdd(((float4*)g_A1) + (size_t)d * (F_HID / 4) + c4, v);
}

// ---------------- GEMM2: H2' = (relu(A1)@W2)*dinv ; out = H2'*dinv + b2 ------
__global__ void __launch_bounds__(256) k_gemm2(const float* __restrict__ W2,
                                               const float* __restrict__ b2,
                                               float* __restrict__ out, int N) {
    __shared__ float At[128][F_HID + 4];
    __shared__ float Ws[F_HID * F_OUT];

    const int tid = threadIdx.x;
    for (int i = tid; i < F_HID * F_OUT; i += 256) Ws[i] = W2[i];

    const int row0 = blockIdx.x * 128;
#pragma unroll
    for (int it = 0; it < 8; it++) {
        int idx = it * 256 + tid;
        int r   = idx >> 4;
        int c4  = idx & 15;
        int gr  = row0 + r;
        float4 v = (gr < N) ? ((const float4*)g_A1)[(size_t)gr * (F_HID / 4) + c4]
                            : make_float4(0.f, 0.f, 0.f, 0.f);
        v.x = fmaxf(v.x, 0.f); v.y = fmaxf(v.y, 0.f);
        v.z = fmaxf(v.z, 0.f); v.w = fmaxf(v.w, 0.f);
        *(float4*)&At[r][c4 * 4] = v;
    }
    __syncthreads();

    const int r  = tid >> 1;
    const int j0 = (tid & 1) * 8;
    const int gr = row0 + r;
    if (gr >= N) return;

    float acc[8];
#pragma unroll
    for (int j = 0; j < 8; j++) acc[j] = 0.f;
#pragma unroll
    for (int k = 0; k < F_HID; k++) {
        float xv = At[r][k];
#pragma unroll
        for (int j = 0; j < 8; j++) acc[j] += xv * Ws[k * F_OUT + j0 + j];
    }

    float s = g_dinv[gr];
    float4 bb0 = *(const float4*)(b2 + j0);
    float4 bb1 = *(const float4*)(b2 + j0 + 4);
    float4 h0 = make_float4(acc[0] * s, acc[1] * s, acc[2] * s, acc[3] * s);
    float4 h1 = make_float4(acc[4] * s, acc[5] * s, acc[6] * s, acc[7] * s);
    *(float4*)(g_H2 + (size_t)gr * F_OUT + j0)     = h0;
    *(float4*)(g_H2 + (size_t)gr * F_OUT + j0 + 4) = h1;
    float4 o0 = make_float4(h0.x * s + bb0.x, h0.y * s + bb0.y,
                            h0.z * s + bb0.z, h0.w * s + bb0.w);
    float4 o1 = make_float4(h1.x * s + bb1.x, h1.y * s + bb1.y,
                            h1.z * s + bb1.z, h1.w * s + bb1.w);
    *(float4*)(out + (size_t)gr * F_OUT + j0)     = o0;
    *(float4*)(out + (size_t)gr * F_OUT + j0 + 4) = o1;
}

// ---------- layer-2 scatter: out[dst] += H2'[src] * dinv[dst] (float4 atomic) ----
__global__ void k_scatter2(const int* __restrict__ src,
                           const int* __restrict__ dst,
                           float* __restrict__ out, int E, int n) {
    long long t = (long long)blockIdx.x * blockDim.x + threadIdx.x;
    if (t >= (long long)E * (F_OUT / 4)) return;
    int e  = (int)(t >> 2);
    int c4 = (int)(t & 3);
    int s = src[e];
    int d = dst[e];
    if ((unsigned)s >= (unsigned)n || (unsigned)d >= (unsigned)n) return;
    float nrm = g_dinv[d];
    float4 v = ((const float4*)g_H2)[(size_t)s * (F_OUT / 4) + c4];
    v.x *= nrm; v.y *= nrm; v.z *= nrm; v.w *= nrm;
    atomicAdd(((float4*)out) + (size_t)d * (F_OUT / 4) + c4, v);
}

// ---------------- launcher ----------------
extern "C" void kernel_launch(void* const* d_in, const int* in_sizes, int n_in,
                              void* d_out, int out_size) {
    const float* x  = (const float*)d_in[0];
    const int*   ei = (const int*)d_in[1];     // int32 edge_index
    const float* W1 = (const float*)d_in[2];
    const float* b1 = (const float*)d_in[3];
    const float* W2 = (const float*)d_in[4];
    const float* b2 = (const float*)d_in[5];
    float*       out = (float*)d_out;

    const int N = in_sizes[0] / F_IN;
    const int E = in_sizes[1] / 2;
    const int* src = ei;
    const int* dst = ei + E;

    const int T = 256;

    // degree -> dinv ; W1 conversion (independent)
    k_deg_init<<<(N + T - 1) / T, T>>>(N);
    k_deg_count<<<(E + T - 1) / T, T>>>(dst, E, N);
    k_rsqrt<<<(N + T - 1) / T, T>>>(N);
    k_convW1<<<(F_HID * F_IN + T - 1) / T, T>>>(W1);

    // layer 1: tensor-core (mma.sync bf16x3) GEMM + fused epilogue, then scatter
    k_gemm1_mma<<<(N + 63) / 64, 128>>>(x, b1, N);
    {
        long long work = (long long)E * (F_HID / 4);
        k_scatter1<<<(unsigned)((work + T - 1) / T), T>>>(src, dst, E, N);
    }

    // layer 2
    k_gemm2<<<(N + 127) / 128, T>>>(W2, b2, out, N);
    {
        long long work = (long long)E * (F_OUT / 4);
        k_scatter2<<<(unsigned)((work + T - 1) / T), T>>>(src, dst, out, E, N);
    }
}